// round 7
// baseline (speedup 1.0000x reference)
#include <cuda_runtime.h>

#define RR 4
#define ND 81
#define HH 128
#define WW 256
#define CC 128
#define BB 8
#define HW (HH*WW)

#define HT 8                 // tile height
#define WT 16                // tile width
#define PW 8                 // pixels per thread (w)
#define CB 4                 // channels per stage
#define NCHUNK (CC/CB)       // 32
#define NSTG 4               // pipeline ring
#define WROWS (HT + 2*RR)    // 16 warped rows per channel
#define WROW 28              // warped row stride (floats); 24 used
#define XROW 20              // x row stride (floats); 16 used
#define WCH (WROWS*WROW)     // 448
#define XCH (HT*XROW)        // 160
#define CHSZ (WCH + XCH)     // 608 floats / channel
#define STG (CB*CHSZ)        // 2432 floats / stage
#define SMEM_BYTES (NSTG * STG * 4)   // 38912
#define NTHR 144             // 9 di * 8 h * 2 wgroups

typedef unsigned long long u64t;

static __device__ __forceinline__ u64t pk2(float lo, float hi) {
    return __double_as_longlong(__hiloint2double(__float_as_int(hi), __float_as_int(lo)));
}
static __device__ __forceinline__ void fma2(u64t &acc, u64t a, u64t b) {
    asm("fma.rn.f32x2 %0, %1, %2, %0;" : "+l"(acc) : "l"(a), "l"(b));
}
static __device__ __forceinline__ float lo32(u64t v) {
    return __int_as_float(__double2loint(__longlong_as_double(v)));
}
static __device__ __forceinline__ float hi32(u64t v) {
    return __int_as_float(__double2hiint(__longlong_as_double(v)));
}
static __device__ __forceinline__ void cpa16(unsigned dst, const float* src) {
    asm volatile("cp.async.cg.shared.global [%0], [%1], 16;" :: "r"(dst), "l"(src));
}

extern __shared__ __align__(16) float smf[];

__global__ void __launch_bounds__(NTHR, 4)
cost_volume_kernel(const float* __restrict__ gx, const float* __restrict__ gw,
                   float* __restrict__ gout)
{
    const int tid = threadIdx.x;
    const int w0  = blockIdx.x * WT;
    const int h0  = blockIdx.y * HT;
    const int b   = blockIdx.z;

    const float* xb = gx + (size_t)b * CC * HW;
    const float* wb = gw + (size_t)b * CC * HW;
    const unsigned smb = (unsigned)__cvta_generic_to_shared(smf);

    // ---------- staging role: ONE float4 per thread per channel, fully hoisted ----------
    // tid 0..95  : warped halo tile, 16 rows x 6 quads (cols w0-4 .. w0+19)
    // tid 96..127: x tile, 8 rows x 4 quads
    // tid 128+   : idle for staging
    const float* gsrc = nullptr;
    int smoff = 0;
    bool active = false;

    if (tid < 96) {
        const int row = tid / 6, q = tid % 6;
        const int gh   = h0 - RR + row;
        const int gcol = w0 - RR + q * 4;           // quads fully in-range or fully OOB
        smoff = row * WROW + q * 4;
        const bool valid = ((unsigned)gh < HH) && (gcol >= 0) && (gcol + 4 <= WW);
        if (valid) { gsrc = wb + (size_t)gh * WW + gcol; active = true; }
        else {
            // OOB slots are channel-independent: zero once in every ring stage
            #pragma unroll
            for (int s = 0; s < NSTG; s++)
                #pragma unroll
                for (int cc2 = 0; cc2 < CB; cc2++)
                    *(float4*)(smf + s * STG + cc2 * CHSZ + smoff) =
                        make_float4(0.f, 0.f, 0.f, 0.f);
        }
    } else if (tid < 128) {
        const int i = tid - 96;
        const int row = i / 4, q = i % 4;
        smoff = WCH + row * XROW + q * 4;
        gsrc  = xb + (size_t)(h0 + row) * WW + w0 + q * 4;
        active = true;
    }

    unsigned sdst[NSTG];
    #pragma unroll
    for (int s = 0; s < NSTG; s++) sdst[s] = smb + (unsigned)((s * STG + smoff) * 4);

    const float* srcp = gsrc;
    auto do_stage = [&](int chunk, int s) {
        if (chunk < NCHUNK) {
            if (active) {
                #pragma unroll
                for (int cc2 = 0; cc2 < CB; cc2++)
                    cpa16(sdst[s] + (unsigned)(cc2 * CHSZ * 4), srcp + cc2 * HW);
                srcp += CB * HW;
            }
        }
        asm volatile("cp.async.commit_group;" ::: "memory");
    };

    // ---------- compute role ----------
    const int dig = tid % 9;        // di + 4
    const int hwg = tid / 9;        // 0..15
    const int h_i = hwg & 7;
    const int wg  = hwg >> 3;       // 0..1

    const int woff = (h_i + dig) * WROW + wg * PW;  // 16B aligned
    const int xoff = WCH + h_i * XROW + wg * PW;    // 16B aligned

    u64t acc[36];                   // [dj(9)][pixel-pair(4)]
    #pragma unroll
    for (int i = 0; i < 36; i++) acc[i] = 0ULL;

    do_stage(0, 0);
    do_stage(1, 1);
    do_stage(2, 2);

    auto body = [&](int chunk, int stage) {
        asm volatile("cp.async.wait_group 2;" ::: "memory");
        __syncthreads();

        const float* sb = smf + stage * STG;
        #pragma unroll
        for (int cc2 = 0; cc2 < CB; cc2++) {
            const float* base = sb + cc2 * CHSZ;
            const float4* wv4 = (const float4*)(base + woff);
            const float4* xv4 = (const float4*)(base + xoff);

            float wr[16];
            #pragma unroll
            for (int k = 0; k < 4; k++) {
                float4 t = wv4[k];
                wr[4*k+0] = t.x; wr[4*k+1] = t.y; wr[4*k+2] = t.z; wr[4*k+3] = t.w;
            }
            float4 x0 = xv4[0], x1 = xv4[1];
            u64t xv[4];
            xv[0] = pk2(x0.x, x0.y); xv[1] = pk2(x0.z, x0.w);
            xv[2] = pk2(x1.x, x1.y); xv[3] = pk2(x1.z, x1.w);

            #pragma unroll
            for (int p = 0; p < 4; p++) {
                #pragma unroll
                for (int dj = 0; dj < 9; dj++) {
                    fma2(acc[dj * 4 + p], xv[p], pk2(wr[2*p + dj], wr[2*p + dj + 1]));
                }
            }
        }

        do_stage(chunk + 3, (chunk + 3) & (NSTG - 1));
    };

    #pragma unroll 1
    for (int c = 0; c < NCHUNK; c += 4) {
        body(c + 0, 0);
        body(c + 1, 1);
        body(c + 2, 2);
        body(c + 3, 3);
    }

    // ---------- epilogue: scale by 1/(C*81), write 9 dj planes x 8 pixels ----------
    const float sc = 1.0f / (float)(CC * ND);
    float* ob = gout + (((size_t)b * ND + dig * 9) * HH + (h0 + h_i)) * WW + w0 + wg * PW;
    #pragma unroll
    for (int dj = 0; dj < 9; dj++) {
        float* od = ob + (size_t)dj * HW;
        #pragma unroll
        for (int p = 0; p < 4; p++) {
            u64t v = acc[dj * 4 + p];
            float2 r;
            r.x = lo32(v) * sc;
            r.y = hi32(v) * sc;
            *(float2*)(od + 2 * p) = r;
        }
    }
}

extern "C" void kernel_launch(void* const* d_in, const int* in_sizes, int n_in,
                              void* d_out, int out_size) {
    const float* x = (const float*)d_in[0];
    const float* w = (const float*)d_in[1];
    float* out = (float*)d_out;
    cudaFuncSetAttribute(cost_volume_kernel,
                         cudaFuncAttributeMaxDynamicSharedMemorySize, SMEM_BYTES);
    dim3 grid(WW / WT, HH / HT, BB);   // (16, 16, 8) = 2048 blocks
    cost_volume_kernel<<<grid, NTHR, SMEM_BYTES>>>(x, w, out);
}

// round 8
// speedup vs baseline: 1.0384x; 1.0384x over previous
#include <cuda_runtime.h>

#define RR 4
#define ND 81
#define HH 128
#define WW 256
#define CC 128
#define BB 8
#define HW (HH*WW)

#define HT 8                 // tile height
#define WT 16                // tile width
#define PW 4                 // pixels per output (w)
#define CB 4                 // channels per stage
#define NCHUNK (CC/CB)       // 32
#define NSTG 4               // pipeline ring
#define WROWS (HT + 2*RR)    // 16 warped rows per channel
#define WROW 28              // warped row stride (floats); 24 used
#define XROW 20              // x row stride (floats); 16 used
#define WCH (WROWS*WROW)     // 448
#define XCH (HT*XROW)        // 160
#define CHSZ (WCH + XCH)     // 608 floats / channel
#define STG (CB*CHSZ)        // 2432 floats / stage
#define SMEM_BYTES (NSTG * STG * 4)   // 38912
#define NROLE 40             // anti-diagonal pair roles per wgroup
#define NTHR (NROLE*4)       // 160

typedef unsigned long long u64t;

// anti-diagonal pairing: role r -> (h, s, npair); outputs (h, d=s-h) and (h+1, d-1)
__constant__ unsigned char TH[NROLE] = {
    0, 0, 0,2, 0,2, 0,2,4, 0,2,4, 0,2,4,6, 0,2,4,6, 0,2,4,6, 1,3,5,7, 2,4,6, 3,5,7, 4,6, 5,7, 6, 7
};
__constant__ unsigned char TS[NROLE] = {
    0, 1, 2,2, 3,3, 4,4,4, 5,5,5, 6,6,6,6, 7,7,7,7, 8,8,8,8, 9,9,9,9, 10,10,10, 11,11,11, 12,12, 13,13, 14, 15
};
__constant__ unsigned char TNP[NROLE] = {
    1, 2, 2,1, 2,2, 2,2,1, 2,2,2, 2,2,2,1, 2,2,2,2, 2,2,2,2, 2,2,2,1, 2,2,2, 2,2,1, 2,2, 2,1, 2, 1
};

static __device__ __forceinline__ u64t pk2(float lo, float hi) {
    return __double_as_longlong(__hiloint2double(__float_as_int(hi), __float_as_int(lo)));
}
static __device__ __forceinline__ void fma2(u64t &acc, u64t a, u64t b) {
    asm("fma.rn.f32x2 %0, %1, %2, %0;" : "+l"(acc) : "l"(a), "l"(b));
}
static __device__ __forceinline__ float lo32(u64t v) {
    return __int_as_float(__double2loint(__longlong_as_double(v)));
}
static __device__ __forceinline__ float hi32(u64t v) {
    return __int_as_float(__double2hiint(__longlong_as_double(v)));
}
static __device__ __forceinline__ void cpa16(unsigned dst, const float* src) {
    asm volatile("cp.async.cg.shared.global [%0], [%1], 16;" :: "r"(dst), "l"(src));
}

extern __shared__ __align__(16) float smf[];

__global__ void __launch_bounds__(NTHR, 3)
cost_volume_kernel(const float* __restrict__ gx, const float* __restrict__ gw,
                   float* __restrict__ gout)
{
    const int tid = threadIdx.x;
    const int w0  = blockIdx.x * WT;
    const int h0  = blockIdx.y * HT;
    const int b   = blockIdx.z;

    const float* xb = gx + (size_t)b * CC * HW;
    const float* wb = gw + (size_t)b * CC * HW;
    const unsigned smb = (unsigned)__cvta_generic_to_shared(smf);

    // ---------- staging role: ONE float4 per thread per channel, fully hoisted ----------
    // tid 0..95  : warped halo tile, 16 rows x 6 quads (cols w0-4 .. w0+19)
    // tid 96..127: x tile, 8 rows x 4 quads
    const float* gsrc = nullptr;
    int smoff = 0;
    bool active = false;

    if (tid < 96) {
        const int row = tid / 6, q = tid % 6;
        const int gh   = h0 - RR + row;
        const int gcol = w0 - RR + q * 4;
        smoff = row * WROW + q * 4;
        const bool valid = ((unsigned)gh < HH) && (gcol >= 0) && (gcol + 4 <= WW);
        if (valid) { gsrc = wb + (size_t)gh * WW + gcol; active = true; }
        else {
            #pragma unroll
            for (int s = 0; s < NSTG; s++)
                #pragma unroll
                for (int cc2 = 0; cc2 < CB; cc2++)
                    *(float4*)(smf + s * STG + cc2 * CHSZ + smoff) =
                        make_float4(0.f, 0.f, 0.f, 0.f);
        }
    } else if (tid < 128) {
        const int i = tid - 96;
        const int row = i / 4, q = i % 4;
        smoff = WCH + row * XROW + q * 4;
        gsrc  = xb + (size_t)(h0 + row) * WW + w0 + q * 4;
        active = true;
    }

    unsigned sdst[NSTG];
    #pragma unroll
    for (int s = 0; s < NSTG; s++) sdst[s] = smb + (unsigned)((s * STG + smoff) * 4);

    const float* srcp = gsrc;
    auto do_stage = [&](int chunk, int s) {
        if (chunk < NCHUNK) {
            if (active) {
                #pragma unroll
                for (int cc2 = 0; cc2 < CB; cc2++)
                    cpa16(sdst[s] + (unsigned)(cc2 * CHSZ * 4), srcp + cc2 * HW);
                srcp += CB * HW;
            }
        }
        asm volatile("cp.async.commit_group;" ::: "memory");
    };

    // ---------- compute role: anti-diagonal pair ----------
    const int wg  = tid / NROLE;       // 0..3
    const int r   = tid - wg * NROLE;  // 0..39
    const int h_i  = (int)TH[r];
    const int srow = (int)TS[r];       // = h + di + RR (shared warped row)
    const int np   = (int)TNP[r];
    const int h_j  = (h_i + 1 < HT) ? (h_i + 1) : (HT - 1);   // clamp; acc1 discarded if np==1

    const int woff  = srow * WROW + wg * PW;
    const int xoffa = WCH + h_i * XROW + wg * PW;
    const int xoffb = WCH + h_j * XROW + wg * PW;

    u64t acc0[18], acc1[18];           // [dj(9)][pixel-pair(2)] for each output
    #pragma unroll
    for (int i = 0; i < 18; i++) { acc0[i] = 0ULL; acc1[i] = 0ULL; }

    do_stage(0, 0);
    do_stage(1, 1);
    do_stage(2, 2);

    auto body = [&](int chunk, int stage) {
        asm volatile("cp.async.wait_group 2;" ::: "memory");
        __syncthreads();

        const float* sb = smf + stage * STG;
        #pragma unroll
        for (int cc2 = 0; cc2 < CB; cc2++) {
            const float* base = sb + cc2 * CHSZ;
            const float4* wv4 = (const float4*)(base + woff);

            float4 q0 = wv4[0], q1 = wv4[1], q2 = wv4[2];
            float4 xqa = *(const float4*)(base + xoffa);
            float4 xqb = *(const float4*)(base + xoffb);

            // 11 window pairs, built once (even ones are free register pairs)
            u64t pr[11];
            pr[0]  = pk2(q0.x, q0.y);
            pr[1]  = pk2(q0.y, q0.z);
            pr[2]  = pk2(q0.z, q0.w);
            pr[3]  = pk2(q0.w, q1.x);
            pr[4]  = pk2(q1.x, q1.y);
            pr[5]  = pk2(q1.y, q1.z);
            pr[6]  = pk2(q1.z, q1.w);
            pr[7]  = pk2(q1.w, q2.x);
            pr[8]  = pk2(q2.x, q2.y);
            pr[9]  = pk2(q2.y, q2.z);
            pr[10] = pk2(q2.z, q2.w);

            u64t xa[2] = { pk2(xqa.x, xqa.y), pk2(xqa.z, xqa.w) };
            u64t xb2[2] = { pk2(xqb.x, xqb.y), pk2(xqb.z, xqb.w) };

            #pragma unroll
            for (int p = 0; p < 2; p++) {
                #pragma unroll
                for (int dj = 0; dj < 9; dj++) {
                    const int o = dj + 2 * p;
                    fma2(acc0[dj * 2 + p], xa[p],  pr[o]);
                    fma2(acc1[dj * 2 + p], xb2[p], pr[o]);
                }
            }
        }

        do_stage(chunk + 3, (chunk + 3) & (NSTG - 1));
    };

    #pragma unroll 1
    for (int c = 0; c < NCHUNK; c += 4) {
        body(c + 0, 0);
        body(c + 1, 1);
        body(c + 2, 2);
        body(c + 3, 3);
    }

    // ---------- epilogue ----------
    const float sc = 1.0f / (float)(CC * ND);
    const int d0 = srow - h_i;         // dig for out0 (0..8)

    {   // out0: (h_i, d0)
        float* ob = gout + (((size_t)b * ND + d0 * 9) * HH + (h0 + h_i)) * WW + w0 + wg * PW;
        #pragma unroll
        for (int dj = 0; dj < 9; dj++) {
            float* od = ob + (size_t)dj * HW;
            #pragma unroll
            for (int p = 0; p < 2; p++) {
                u64t v = acc0[dj * 2 + p];
                float2 r2; r2.x = lo32(v) * sc; r2.y = hi32(v) * sc;
                *(float2*)(od + 2 * p) = r2;
            }
        }
    }
    if (np == 2) {   // out1: (h_i+1, d0-1)
        float* ob = gout + (((size_t)b * ND + (d0 - 1) * 9) * HH + (h0 + h_i + 1)) * WW + w0 + wg * PW;
        #pragma unroll
        for (int dj = 0; dj < 9; dj++) {
            float* od = ob + (size_t)dj * HW;
            #pragma unroll
            for (int p = 0; p < 2; p++) {
                u64t v = acc1[dj * 2 + p];
                float2 r2; r2.x = lo32(v) * sc; r2.y = hi32(v) * sc;
                *(float2*)(od + 2 * p) = r2;
            }
        }
    }
}

extern "C" void kernel_launch(void* const* d_in, const int* in_sizes, int n_in,
                              void* d_out, int out_size) {
    const float* x = (const float*)d_in[0];
    const float* w = (const float*)d_in[1];
    float* out = (float*)d_out;
    cudaFuncSetAttribute(cost_volume_kernel,
                         cudaFuncAttributeMaxDynamicSharedMemorySize, SMEM_BYTES);
    dim3 grid(WW / WT, HH / HT, BB);   // (16, 16, 8) = 2048 blocks
    cost_volume_kernel<<<grid, NTHR, SMEM_BYTES>>>(x, w, out);
}

// round 9
// speedup vs baseline: 1.1263x; 1.0847x over previous
#include <cuda_runtime.h>

#define RR 4
#define ND 81
#define HH 128
#define WW 256
#define CC 128
#define BB 8
#define HW (HH*WW)

#define HT 8                 // tile height
#define WT 16                // tile width
#define PW 4                 // pixels per thread (w)
#define CB 8                 // channels per stage
#define NCHUNK (CC/CB)       // 16
#define NSTG 3               // pipeline ring (1 barrier per chunk is safe at >=3)
#define WROWS (HT + 2*RR)    // 16 warped rows per channel
#define WROW 28              // warped row stride (floats); 24 used
#define XROW 20              // x row stride (floats); 16 used
#define WCH (WROWS*WROW)     // 448
#define XCH (HT*XROW)        // 160
#define CHSZ (WCH + XCH)     // 608 floats / channel
#define STG (CB*CHSZ)        // 4864 floats / stage
#define SMEM_BYTES (NSTG * STG * 4)   // 58368
#define NTHR 288             // 9 di * 8 h * 4 wgroups

typedef unsigned long long u64t;

static __device__ __forceinline__ u64t pk2(float lo, float hi) {
    return __double_as_longlong(__hiloint2double(__float_as_int(hi), __float_as_int(lo)));
}
static __device__ __forceinline__ void fma2(u64t &acc, u64t a, u64t b) {
    asm("fma.rn.f32x2 %0, %1, %2, %0;" : "+l"(acc) : "l"(a), "l"(b));
}
static __device__ __forceinline__ float lo32(u64t v) {
    return __int_as_float(__double2loint(__longlong_as_double(v)));
}
static __device__ __forceinline__ float hi32(u64t v) {
    return __int_as_float(__double2hiint(__longlong_as_double(v)));
}
static __device__ __forceinline__ void cpa16(unsigned dst, const float* src) {
    asm volatile("cp.async.cg.shared.global [%0], [%1], 16;" :: "r"(dst), "l"(src));
}

extern __shared__ __align__(16) float smf[];

__global__ void __launch_bounds__(NTHR, 3)
cost_volume_kernel(const float* __restrict__ gx, const float* __restrict__ gw,
                   float* __restrict__ gout)
{
    const int tid = threadIdx.x;
    const int w0  = blockIdx.x * WT;
    const int h0  = blockIdx.y * HT;
    const int b   = blockIdx.z;

    const float* xb = gx + (size_t)b * CC * HW;
    const float* wb = gw + (size_t)b * CC * HW;
    const unsigned smb = (unsigned)__cvta_generic_to_shared(smf);

    // ---------- staging role: ONE float4 per thread per channel, fully hoisted ----------
    // tid 0..95  : warped halo tile, 16 rows x 6 quads (cols w0-4 .. w0+19)
    // tid 96..127: x tile, 8 rows x 4 quads
    const float* gsrc = nullptr;
    int smoff = 0;
    bool active = false;

    if (tid < 96) {
        const int row = tid / 6, q = tid % 6;
        const int gh   = h0 - RR + row;
        const int gcol = w0 - RR + q * 4;           // quads fully in-range or fully OOB
        smoff = row * WROW + q * 4;
        const bool valid = ((unsigned)gh < HH) && (gcol >= 0) && (gcol + 4 <= WW);
        if (valid) { gsrc = wb + (size_t)gh * WW + gcol; active = true; }
        else {
            // OOB slots are channel-independent: zero once in every ring stage
            for (int s = 0; s < NSTG; s++)
                for (int cc2 = 0; cc2 < CB; cc2++)
                    *(float4*)(smf + s * STG + cc2 * CHSZ + smoff) =
                        make_float4(0.f, 0.f, 0.f, 0.f);
        }
    } else if (tid < 128) {
        const int i = tid - 96;
        const int row = i / 4, q = i % 4;
        smoff = WCH + row * XROW + q * 4;
        gsrc  = xb + (size_t)(h0 + row) * WW + w0 + q * 4;
        active = true;
    }

    unsigned sdst[NSTG];
    #pragma unroll
    for (int s = 0; s < NSTG; s++) sdst[s] = smb + (unsigned)((s * STG + smoff) * 4);

    const float* srcp = gsrc;
    auto do_stage = [&](int chunk, int s) {
        if (chunk < NCHUNK) {
            if (active) {
                #pragma unroll
                for (int cc2 = 0; cc2 < CB; cc2++)
                    cpa16(sdst[s] + (unsigned)(cc2 * CHSZ * 4), srcp + cc2 * HW);
                srcp += CB * HW;
            }
        }
        asm volatile("cp.async.commit_group;" ::: "memory");
    };

    // ---------- compute role ----------
    const int dig = tid % 9;        // di + 4
    const int hwg = tid / 9;        // 0..31
    const int h_i = hwg & 7;
    const int wg  = hwg >> 3;       // 0..3

    const int woff = (h_i + dig) * WROW + wg * PW;  // 16B aligned
    const int xoff = WCH + h_i * XROW + wg * PW;    // 16B aligned

    u64t acc[18];                   // [dj(9)][pixel-pair(2)]
    #pragma unroll
    for (int i = 0; i < 18; i++) acc[i] = 0ULL;

    do_stage(0, 0);
    do_stage(1, 1);

    int st  = 0;                    // stage being consumed
    int st2 = 2;                    // stage being refilled (chunk+2)

    #pragma unroll 1
    for (int chunk = 0; chunk < NCHUNK; chunk++) {
        asm volatile("cp.async.wait_group 1;" ::: "memory");
        __syncthreads();

        const float* sb = smf + st * STG;
        #pragma unroll
        for (int cc2 = 0; cc2 < CB; cc2++) {
            const float* base = sb + cc2 * CHSZ;
            const float4* wv4 = (const float4*)(base + woff);

            float4 q0 = wv4[0], q1 = wv4[1], q2 = wv4[2];
            float4 xq = *(const float4*)(base + xoff);

            // 11 window pairs: even ones are free register pairs from the quads,
            // the 5 odd ones are built once and shared by both p positions.
            u64t pr[11];
            pr[0]  = pk2(q0.x, q0.y);
            pr[1]  = pk2(q0.y, q0.z);
            pr[2]  = pk2(q0.z, q0.w);
            pr[3]  = pk2(q0.w, q1.x);
            pr[4]  = pk2(q1.x, q1.y);
            pr[5]  = pk2(q1.y, q1.z);
            pr[6]  = pk2(q1.z, q1.w);
            pr[7]  = pk2(q1.w, q2.x);
            pr[8]  = pk2(q2.x, q2.y);
            pr[9]  = pk2(q2.y, q2.z);
            pr[10] = pk2(q2.z, q2.w);

            u64t xv[2] = { pk2(xq.x, xq.y), pk2(xq.z, xq.w) };

            #pragma unroll
            for (int p = 0; p < 2; p++) {
                #pragma unroll
                for (int dj = 0; dj < 9; dj++) {
                    fma2(acc[dj * 2 + p], xv[p], pr[dj + 2 * p]);
                }
            }
        }

        do_stage(chunk + 2, st2);
        st  = (st  + 1 == NSTG) ? 0 : st  + 1;
        st2 = (st2 + 1 == NSTG) ? 0 : st2 + 1;
    }

    // ---------- epilogue: scale by 1/(C*81), write 9 dj planes x 4 pixels ----------
    const float sc = 1.0f / (float)(CC * ND);
    float* ob = gout + (((size_t)b * ND + dig * 9) * HH + (h0 + h_i)) * WW + w0 + wg * PW;
    #pragma unroll
    for (int dj = 0; dj < 9; dj++) {
        float* od = ob + (size_t)dj * HW;
        #pragma unroll
        for (int p = 0; p < 2; p++) {
            u64t v = acc[dj * 2 + p];
            float2 r2;
            r2.x = lo32(v) * sc;
            r2.y = hi32(v) * sc;
            *(float2*)(od + 2 * p) = r2;
        }
    }
}

extern "C" void kernel_launch(void* const* d_in, const int* in_sizes, int n_in,
                              void* d_out, int out_size) {
    const float* x = (const float*)d_in[0];
    const float* w = (const float*)d_in[1];
    float* out = (float*)d_out;
    cudaFuncSetAttribute(cost_volume_kernel,
                         cudaFuncAttributeMaxDynamicSharedMemorySize, SMEM_BYTES);
    dim3 grid(WW / WT, HH / HT, BB);   // (16, 16, 8) = 2048 blocks
    cost_volume_kernel<<<grid, NTHR, SMEM_BYTES>>>(x, w, out);
}

// round 10
// speedup vs baseline: 1.1678x; 1.0369x over previous
#include <cuda_runtime.h>

#define RR 4
#define ND 81
#define HH 128
#define WW 256
#define CC 128
#define BB 8
#define HW (HH*WW)

#define HT 8                 // tile height
#define WT 16                // tile width
#define PW 4                 // pixels per thread (w)
#define CB 8                 // channels per stage
#define NCHUNK (CC/CB)       // 16
#define NSTG 3               // pipeline ring
#define WROWS (HT + 2*RR)    // 16
#define WROW 28              // warped row stride (floats)
#define XROW 20              // x row stride (floats)
#define WCH (WROWS*WROW)     // 448
#define XCH (HT*XROW)        // 160
#define CHSZ (WCH + XCH)     // 608 floats / channel
#define STG (CB*CHSZ)        // 4864 floats / stage
#define MBAR_OFF (NSTG*STG*4)            // byte offset of mbarriers
#define SMEM_BYTES (MBAR_OFF + 64)
#define NTHR 320             // 9 compute warps (288) + 1 producer warp (32)

typedef unsigned long long u64t;

static __device__ __forceinline__ u64t pk2(float lo, float hi) {
    return __double_as_longlong(__hiloint2double(__float_as_int(hi), __float_as_int(lo)));
}
static __device__ __forceinline__ void fma2(u64t &acc, u64t a, u64t b) {
    asm("fma.rn.f32x2 %0, %1, %2, %0;" : "+l"(acc) : "l"(a), "l"(b));
}
static __device__ __forceinline__ float lo32(u64t v) {
    return __int_as_float(__double2loint(__longlong_as_double(v)));
}
static __device__ __forceinline__ float hi32(u64t v) {
    return __int_as_float(__double2hiint(__longlong_as_double(v)));
}
static __device__ __forceinline__ void cpa16(unsigned dst, const float* src) {
    asm volatile("cp.async.cg.shared.global [%0], [%1], 16;" :: "r"(dst), "l"(src));
}
static __device__ __forceinline__ void mb_init(unsigned a, unsigned cnt) {
    asm volatile("mbarrier.init.shared.b64 [%0], %1;" :: "r"(a), "r"(cnt) : "memory");
}
static __device__ __forceinline__ void mb_arrive(unsigned a) {
    asm volatile("mbarrier.arrive.release.cta.shared::cta.b64 _, [%0];" :: "r"(a) : "memory");
}
static __device__ __forceinline__ void mb_wait(unsigned a, unsigned parity) {
    asm volatile(
        "{\n\t.reg .pred P1;\n\t"
        "WL_%=:\n\t"
        "mbarrier.try_wait.parity.acquire.cta.shared::cta.b64 P1, [%0], %1, 0x989680;\n\t"
        "@P1 bra.uni WD_%=;\n\t"
        "bra.uni WL_%=;\n\t"
        "WD_%=:\n\t}"
        :: "r"(a), "r"(parity) : "memory");
}

extern __shared__ __align__(16) float smf[];

__global__ void __launch_bounds__(NTHR, 3)
cost_volume_kernel(const float* __restrict__ gx, const float* __restrict__ gw,
                   float* __restrict__ gout)
{
    const int tid = threadIdx.x;
    const int w0  = blockIdx.x * WT;
    const int h0  = blockIdx.y * HT;
    const int b   = blockIdx.z;

    const float* xb = gx + (size_t)b * CC * HW;
    const float* wb = gw + (size_t)b * CC * HW;
    const unsigned smb = (unsigned)__cvta_generic_to_shared(smf);

    // mbarriers: full[s] at MBAR_OFF + s*16, empty[s] at +8
    const unsigned mbF0 = smb + MBAR_OFF;
    if (tid == 0) {
        #pragma unroll
        for (int s = 0; s < NSTG; s++) {
            mb_init(mbF0 + s * 16, 32);      // full: 32 producer lanes arrive
            mb_init(mbF0 + s * 16 + 8, 9);   // empty: 9 consumer warp-elects
        }
    }
    // OOB warped slots are channel-independent: zero once in every ring stage
    if (tid < 96) {
        const int row = tid / 6, q = tid % 6;
        const int gh   = h0 - RR + row;
        const int gcol = w0 - RR + q * 4;
        if (!(((unsigned)gh < HH) && (gcol >= 0) && (gcol + 4 <= WW))) {
            const int so = row * WROW + q * 4;
            for (int s = 0; s < NSTG; s++)
                for (int cc2 = 0; cc2 < CB; cc2++)
                    *(float4*)(smf + s * STG + cc2 * CHSZ + so) =
                        make_float4(0.f, 0.f, 0.f, 0.f);
        }
    }
    __syncthreads();

    if (tid >= 288) {
        // ================= producer warp =================
        const int lane = tid - 288;
        const float* src[4]; unsigned doff[4]; bool val[4];
        #pragma unroll
        for (int k = 0; k < 4; k++) {
            const int it = lane + 32 * k;
            if (it < 96) {                      // warped halo: 16 rows x 6 quads
                const int row = it / 6, q = it % 6;
                const int gh   = h0 - RR + row;
                const int gcol = w0 - RR + q * 4;
                doff[k] = (unsigned)((row * WROW + q * 4) * 4);
                val[k]  = ((unsigned)gh < HH) && (gcol >= 0) && (gcol + 4 <= WW);
                src[k]  = val[k] ? (wb + (size_t)gh * WW + gcol) : wb;
            } else {                            // x tile: 8 rows x 4 quads
                const int i = it - 96;
                const int row = i / 4, q = i % 4;
                doff[k] = (unsigned)((WCH + row * XROW + q * 4) * 4);
                src[k]  = xb + (size_t)(h0 + row) * WW + w0 + q * 4;
                val[k]  = true;
            }
        }

        int es = 0, eph = 0;     // empty-wait cursor (engages at chunk NSTG)
        int ps = 0, prev = 0;    // current / previous stage
        #pragma unroll 1
        for (int chunk = 0; chunk < NCHUNK; chunk++) {
            if (chunk >= NSTG) {
                mb_wait(mbF0 + es * 16 + 8, (unsigned)eph);
                if (++es == NSTG) { es = 0; eph ^= 1; }
            }
            const unsigned sb = smb + (unsigned)(ps * STG * 4);
            #pragma unroll
            for (int cc = 0; cc < CB; cc++) {
                #pragma unroll
                for (int k = 0; k < 4; k++)
                    if (val[k]) cpa16(sb + doff[k] + (unsigned)(cc * CHSZ * 4),
                                      src[k] + cc * HW);
            }
            #pragma unroll
            for (int k = 0; k < 4; k++) src[k] += CB * HW;
            asm volatile("cp.async.commit_group;" ::: "memory");
            if (chunk >= 1) {
                asm volatile("cp.async.wait_group 1;" ::: "memory");
                mb_arrive(mbF0 + prev * 16);
            }
            prev = ps;
            if (++ps == NSTG) ps = 0;
        }
        asm volatile("cp.async.wait_group 0;" ::: "memory");
        mb_arrive(mbF0 + prev * 16);
    } else {
        // ================= consumer warps =================
        const int dig = tid % 9;        // di + 4
        const int hwg = tid / 9;        // 0..31
        const int h_i = hwg & 7;
        const int wg  = hwg >> 3;       // 0..3

        const int woff = (h_i + dig) * WROW + wg * PW;
        const int xoff = WCH + h_i * XROW + wg * PW;

        u64t acc[18];                   // [dj(9)][pixel-pair(2)]
        #pragma unroll
        for (int i = 0; i < 18; i++) acc[i] = 0ULL;

        int st = 0, ph = 0;
        #pragma unroll 1
        for (int chunk = 0; chunk < NCHUNK; chunk++) {
            mb_wait(mbF0 + st * 16, (unsigned)ph);

            const float* sb = smf + st * STG;
            #pragma unroll
            for (int cc2 = 0; cc2 < CB; cc2++) {
                const float* base = sb + cc2 * CHSZ;
                const float4* wv4 = (const float4*)(base + woff);

                float4 q0 = wv4[0], q1 = wv4[1], q2 = wv4[2];
                float4 xq = *(const float4*)(base + xoff);

                u64t pr[11];
                pr[0]  = pk2(q0.x, q0.y);
                pr[1]  = pk2(q0.y, q0.z);
                pr[2]  = pk2(q0.z, q0.w);
                pr[3]  = pk2(q0.w, q1.x);
                pr[4]  = pk2(q1.x, q1.y);
                pr[5]  = pk2(q1.y, q1.z);
                pr[6]  = pk2(q1.z, q1.w);
                pr[7]  = pk2(q1.w, q2.x);
                pr[8]  = pk2(q2.x, q2.y);
                pr[9]  = pk2(q2.y, q2.z);
                pr[10] = pk2(q2.z, q2.w);

                u64t xv[2] = { pk2(xq.x, xq.y), pk2(xq.z, xq.w) };

                #pragma unroll
                for (int p = 0; p < 2; p++) {
                    #pragma unroll
                    for (int dj = 0; dj < 9; dj++) {
                        fma2(acc[dj * 2 + p], xv[p], pr[dj + 2 * p]);
                    }
                }
            }

            if ((tid & 31) == 0) mb_arrive(mbF0 + st * 16 + 8);
            if (++st == NSTG) { st = 0; ph ^= 1; }
        }

        // epilogue: scale by 1/(C*81), write 9 dj planes x 4 pixels
        const float sc = 1.0f / (float)(CC * ND);
        float* ob = gout + (((size_t)b * ND + dig * 9) * HH + (h0 + h_i)) * WW + w0 + wg * PW;
        #pragma unroll
        for (int dj = 0; dj < 9; dj++) {
            float* od = ob + (size_t)dj * HW;
            #pragma unroll
            for (int p = 0; p < 2; p++) {
                u64t v = acc[dj * 2 + p];
                float2 r2;
                r2.x = lo32(v) * sc;
                r2.y = hi32(v) * sc;
                *(float2*)(od + 2 * p) = r2;
            }
        }
    }
}

extern "C" void kernel_launch(void* const* d_in, const int* in_sizes, int n_in,
                              void* d_out, int out_size) {
    const float* x = (const float*)d_in[0];
    const float* w = (const float*)d_in[1];
    float* out = (float*)d_out;
    cudaFuncSetAttribute(cost_volume_kernel,
                         cudaFuncAttributeMaxDynamicSharedMemorySize, SMEM_BYTES);
    dim3 grid(WW / WT, HH / HT, BB);   // (16, 16, 8) = 2048 blocks
    cost_volume_kernel<<<grid, NTHR, SMEM_BYTES>>>(x, w, out);
}